// round 1
// baseline (speedup 1.0000x reference)
#include <cuda_runtime.h>
#include <math.h>

#define NN 8192
#define DD 256
#define UU 128
#define BM 64
#define BN 64

// ---------------- device scratch (no allocations allowed) ----------------
__device__ float g_x [NN * UU];   // x = expmap0(features @ kernel), row-major
__device__ float g_xT[UU * NN];   // transpose of g_x
__device__ float g_x2[NN];        // ||x_i||^2
__device__ float g_buf[NN * UU];  // stage1 temp (u), then flash output (mx)

// ============================================================
// Stage 1: u = features @ kernel   [8192,256]@[256,128]
// 512 blocks x 256 threads, 16 rows per block
// ============================================================
__global__ __launch_bounds__(256) void k_gemmA(const float* __restrict__ feat,
                                               const float* __restrict__ W) {
    __shared__ float fs[16][DD];   // 16 KB
    int tid = threadIdx.x;
    int r0  = blockIdx.x * 16;
    for (int idx = tid; idx < 16 * DD; idx += 256)
        fs[idx >> 8][idx & 255] = feat[(size_t)(r0 + (idx >> 8)) * DD + (idx & 255)];
    __syncthreads();

    int col = tid & 127;
    int rg  = tid >> 7;            // 0/1 -> rows rg*8 .. rg*8+7
    float acc[8] = {0.f,0.f,0.f,0.f,0.f,0.f,0.f,0.f};
    for (int d = 0; d < DD; d++) {
        float kv = W[d * UU + col];
        #pragma unroll
        for (int r = 0; r < 8; r++)
            acc[r] = fmaf(fs[rg * 8 + r][d], kv, acc[r]);
    }
    #pragma unroll
    for (int r = 0; r < 8; r++)
        g_buf[(size_t)(r0 + rg * 8 + r) * UU + col] = acc[r];
}

// ============================================================
// block reduction helper (128-thread blocks, 4 warps)
// ============================================================
__device__ __forceinline__ float blockReduce128(float v, volatile float* sm) {
    #pragma unroll
    for (int o = 16; o > 0; o >>= 1) v += __shfl_xor_sync(0xffffffffu, v, o);
    if ((threadIdx.x & 31) == 0) sm[threadIdx.x >> 5] = v;
    __syncthreads();
    float r = sm[0] + sm[1] + sm[2] + sm[3];
    __syncthreads();
    return r;
}

// ============================================================
// Stage 2: x = expmap0(u); also write xT and x2 = sum(x*x)
// one row per 128-thread block
// ============================================================
__global__ __launch_bounds__(128) void k_expmap() {
    __shared__ float sm[4];
    int row = blockIdx.x, t = threadIdx.x;
    float v  = g_buf[(size_t)row * UU + t];
    float n2 = blockReduce128(v * v, sm);
    float n  = fmaxf(sqrtf(n2), 1e-15f);
    float fac = tanhf(n) / n;
    float xv = fac * v;
    g_x [(size_t)row * UU + t] = xv;
    g_xT[(size_t)t * NN + row] = xv;
    float s2 = blockReduce128(xv * xv, sm);
    if (t == 0) g_x2[row] = s2;
}

// ============================================================
// Stage 3: fused flash attention over hyperbolic distances.
// grid = 128 blocks (64 rows each), 256 threads.
//   GEMM1: S[64,64] = Xi . Xj^T  (dot over 128 feature dims)
//   score: w = (den+sqrt(num))/(den-sqrt(num)) masked by adj / z==0
//   GEMM2: O[64,128] += W * Xj ; row sums of W tracked online
// ============================================================
#define SM_XIT 0
#define SM_XJT (SM_XIT + UU * BM)
#define SM_XJS (SM_XJT + UU * BN)
#define SM_WS  (SM_XJS + BN * UU)
#define SM_X2I (SM_WS + BM * 68)
#define SM_X2J (SM_X2I + BM)
#define SMEM_FLOATS (SM_X2J + BN)
#define SMEM_BYTES (SMEM_FLOATS * 4)

__global__ __launch_bounds__(256) void k_flash(const int* __restrict__ adj) {
    extern __shared__ float smem[];
    float* Xit   = smem + SM_XIT;   // [128][64]  Xit[k][i]
    float* Xjt   = smem + SM_XJT;   // [128][64]  Xjt[k][j]
    float* Xjs   = smem + SM_XJS;   // [64][128]  Xjs[j][k]
    float* Ws    = smem + SM_WS;    // [64][68]   padded
    float* x2i_s = smem + SM_X2I;
    float* x2j_s = smem + SM_X2J;

    int tid = threadIdx.x;
    int tx = tid & 15, ty = tid >> 4;     // 16 x 16 thread grid
    int i0 = blockIdx.x * BM;

    // load Xi tile (transposed, once per block)
    for (int idx = tid; idx < UU * BM; idx += 256) {
        int k = idx >> 6, i = idx & 63;
        Xit[k * 64 + i] = g_xT[(size_t)k * NN + i0 + i];
    }
    if (tid < BM) x2i_s[tid] = g_x2[i0 + tid];
    __syncthreads();

    float x2i[4];
    #pragma unroll
    for (int r = 0; r < 4; r++) x2i[r] = x2i_s[ty * 4 + r];

    float o[4][8];
    #pragma unroll
    for (int r = 0; r < 4; r++)
        #pragma unroll
        for (int d = 0; d < 8; d++) o[r][d] = 0.f;
    float rsum[4] = {0.f, 0.f, 0.f, 0.f};

    for (int j0 = 0; j0 < NN; j0 += BN) {
        __syncthreads();   // previous GEMM2 done reading Xjs/Ws
        // ---- load Xj tiles (both layouts) + x2j ----
        for (int idx = tid; idx < UU * BN; idx += 256) {
            int k = idx >> 6, j = idx & 63;
            Xjt[k * 64 + j] = g_xT[(size_t)k * NN + j0 + j];
        }
        for (int idx = tid; idx < BN * (UU / 4); idx += 256) {
            int j = idx >> 5, kq = idx & 31;
            float4 v = ((const float4*)g_x)[(size_t)(j0 + j) * (UU / 4) + kq];
            *(float4*)(Xjs + j * UU + kq * 4) = v;
        }
        if (tid < BN) x2j_s[tid] = g_x2[j0 + tid];
        // prefetch adjacency (int4 per row of the 4x4 score tile)
        int4 av[4];
        #pragma unroll
        for (int r = 0; r < 4; r++)
            av[r] = *(const int4*)&adj[(size_t)(i0 + ty * 4 + r) * NN + j0 + tx * 4];
        __syncthreads();

        // ---- GEMM1: scores ----
        float s[4][4];
        #pragma unroll
        for (int r = 0; r < 4; r++)
            #pragma unroll
            for (int c = 0; c < 4; c++) s[r][c] = 0.f;

        #pragma unroll 4
        for (int k = 0; k < UU; k++) {
            float4 a4 = *(const float4*)(Xit + k * 64 + ty * 4);
            float4 b4 = *(const float4*)(Xjt + k * 64 + tx * 4);
            float af[4] = {a4.x, a4.y, a4.z, a4.w};
            float bf[4] = {b4.x, b4.y, b4.z, b4.w};
            #pragma unroll
            for (int r = 0; r < 4; r++)
                #pragma unroll
                for (int c = 0; c < 4; c++)
                    s[r][c] = fmaf(af[r], bf[c], s[r][c]);
        }

        // ---- score function:  w = exp(dist) = (den + sq) / (den - sq) ----
        float x2jv[4];
        #pragma unroll
        for (int c = 0; c < 4; c++) x2jv[c] = x2j_s[tx * 4 + c];

        #pragma unroll
        for (int r = 0; r < 4; r++) {
            int am[4] = {av[r].x, av[r].y, av[r].z, av[r].w};
            float wv[4];
            #pragma unroll
            for (int c = 0; c < 4; c++) {
                float xy = s[r][c];
                float A  = 1.f - 2.f * xy + x2jv[c];
                float B  = 1.f - x2i[r];
                float num = fmaf(A * A, x2i[r],
                             fmaf(-2.f * A * B, xy, B * B * x2jv[c]));
                num = fmaxf(num, 0.f);
                float den = fmaxf(fmaf(x2i[r], x2jv[c], 1.f - 2.f * xy), 1e-15f);
                float sq  = sqrtf(num);
                float w;
                if (sq < (1.f - 1e-7f) * den)   // z below artanh clip
                    w = (den + sq) / (den - sq);
                else                             // z clipped to 1 - 1e-7
                    w = (2.f - 1e-7f) / 1e-7f;
                if (am[c] == 0 || !(sq > 0.f)) w = 0.f;   // adjacency / dist==0 mask
                wv[c] = w;
                rsum[r] += w;
            }
            *(float4*)(Ws + (ty * 4 + r) * 68 + tx * 4) =
                make_float4(wv[0], wv[1], wv[2], wv[3]);
        }
        __syncthreads();

        // ---- GEMM2: O += W * Xj ----
        #pragma unroll 2
        for (int j = 0; j < BN; j++) {
            float4 b0 = *(const float4*)(Xjs + j * UU + tx * 8);
            float4 b1 = *(const float4*)(Xjs + j * UU + tx * 8 + 4);
            float bf[8] = {b0.x, b0.y, b0.z, b0.w, b1.x, b1.y, b1.z, b1.w};
            #pragma unroll
            for (int r = 0; r < 4; r++) {
                float w = Ws[(ty * 4 + r) * 68 + j];
                #pragma unroll
                for (int d = 0; d < 8; d++)
                    o[r][d] = fmaf(w, bf[d], o[r][d]);
            }
        }
    }

    // ---- row-sum reduction across tx, normalize, write mx ----
    __syncthreads();
    #pragma unroll
    for (int r = 0; r < 4; r++) Ws[(ty * 4 + r) * 68 + tx] = rsum[r];
    __syncthreads();
    float inv[4];
    #pragma unroll
    for (int r = 0; r < 4; r++) {
        float t = 0.f;
        #pragma unroll
        for (int q = 0; q < 16; q++) t += Ws[(ty * 4 + r) * 68 + q];
        inv[r] = 1.f / t;
    }
    #pragma unroll
    for (int r = 0; r < 4; r++)
        #pragma unroll
        for (int d = 0; d < 8; d++)
            g_buf[(size_t)(i0 + ty * 4 + r) * UU + tx * 8 + d] = o[r][d] * inv[r];
}

// ============================================================
// Stage 4: hyperbolic rescale + mobius bias add, one row/block
// ============================================================
__global__ __launch_bounds__(128) void k_epilogue(const float* __restrict__ bias,
                                                  float* __restrict__ out) {
    __shared__ float sm[4];
    int row = blockIdx.x, t = threadIdx.x;

    float m   = g_buf[(size_t)row * UU + t];
    float mn2 = blockReduce128(m * m, sm);
    float x2i = g_x2[row];
    float x_n  = fmaxf(sqrtf(x2i), 1e-15f);
    float mx_n = fmaxf(sqrtf(mn2), 1e-15f);
    float xa   = fminf(x_n, 1.f - 1e-7f);
    float art  = 0.5f * (log1pf(xa) - log1pf(-xa));       // artanh
    float alpha = tanhf(mx_n / x_n * art) / mx_n;
    float ov = alpha * m;

    // b = expmap0(bias)
    float bv  = bias[t];
    float bn2 = blockReduce128(bv * bv, sm);
    float bn  = fmaxf(sqrtf(bn2), 1e-15f);
    float bvx = tanhf(bn) / bn * bv;

    // mobius_add(ov, bvx)
    float y2  = blockReduce128(bvx * bvx, sm);
    float xy  = blockReduce128(ov * bvx, sm);
    float x2o = blockReduce128(ov * ov, sm);
    float cx  = 1.f + 2.f * xy + y2;
    float cy  = 1.f - x2o;
    float den = fmaxf(fmaf(x2o, y2, 1.f + 2.f * xy), 1e-15f);
    out[(size_t)row * UU + t] = (cx * ov + cy * bvx) / den;
}

// ============================================================
extern "C" void kernel_launch(void* const* d_in, const int* in_sizes, int n_in,
                              void* d_out, int out_size) {
    const float* feat = (const float*)d_in[0];   // [8192,256]
    const int*   adj  = (const int*)  d_in[1];   // [8192,8192]
    const float* W    = (const float*)d_in[2];   // [256,128]
    const float* bias = (const float*)d_in[3];   // [128]
    float* out = (float*)d_out;

    cudaFuncSetAttribute(k_flash, cudaFuncAttributeMaxDynamicSharedMemorySize,
                         SMEM_BYTES);

    k_gemmA   <<<NN / 16, 256>>>(feat, W);
    k_expmap  <<<NN, 128>>>();
    k_flash   <<<NN / BM, 256, SMEM_BYTES>>>(adj);
    k_epilogue<<<NN, 128>>>(bias, out);
}